// round 6
// baseline (speedup 1.0000x reference)
#include <cuda_runtime.h>
#include <cuda_bf16.h>

// PCEN via exact parallel linear-recurrence scan (constant per-row decay a=1-s).
// R6: TWO rows per CTA, fully fused. All 4 LDG.128 issued up front (2x MLP);
// warp scan / level-3 scan / MUFU epilogue run two independent dependency
// chains in one instruction stream, overlapping DRAM and MUFU phases that the
// one-row bulk-synchronous version serialized.

#define TT    8000
#define EPT   8
#define NTH   1024
#define NWARP (NTH/32)
#define ALPHA_C 0.98f
#define DELTA_C 2.0f
#define EPS_C   1e-6f
#define SQRT_DELTA 1.41421356237f
#define LOG2E 1.44269504089f

__device__ __forceinline__ float f_lg2(float x) {
    float r; asm("lg2.approx.f32 %0, %1;" : "=f"(r) : "f"(x)); return r;
}
__device__ __forceinline__ float f_ex2(float x) {
    float r; asm("ex2.approx.f32 %0, %1;" : "=f"(r) : "f"(x)); return r;
}
__device__ __forceinline__ float f_sqrt(float x) {
    float r; asm("sqrt.approx.f32 %0, %1;" : "=f"(r) : "f"(x)); return r;
}

__global__ __launch_bounds__(NTH, 2)
void pcen_kernel(const float* __restrict__ x,
                 const float* __restrict__ log_s,
                 float* __restrict__ out,
                 int F, int rows)
{
    const int rowA = blockIdx.x * 2;
    int rowB = rowA + 1; if (rowB >= rows) rowB = rowA;   // clamp (benign dup)

    const float sA = f_ex2(LOG2E * __ldg(log_s + (rowA % F)));
    const float sB = f_ex2(LOG2E * __ldg(log_s + (rowB % F)));
    const float aA = 1.0f - sA;
    const float aB = 1.0f - sB;

    const int t    = threadIdx.x;
    const int base = t * EPT;
    const bool active = (base < TT);
    const int lane = t & 31;
    const int wid  = t >> 5;

    __shared__ float totA[NWARP], totB[NWARP];
    __shared__ float x0A, x0B;

    // ---- issue ALL loads up front (4x LDG.128 in flight) ----
    float xa[EPT], xb[EPT];
    if (active) {
        const float4* pA = (const float4*)(x + (long long)rowA * TT + base);
        const float4* pB = (const float4*)(x + (long long)rowB * TT + base);
        float4 a0 = pA[0], a1 = pA[1];
        float4 b0 = pB[0], b1 = pB[1];
        xa[0]=a0.x; xa[1]=a0.y; xa[2]=a0.z; xa[3]=a0.w;
        xa[4]=a1.x; xa[5]=a1.y; xa[6]=a1.z; xa[7]=a1.w;
        xb[0]=b0.x; xb[1]=b0.y; xb[2]=b0.z; xb[3]=b0.w;
        xb[4]=b1.x; xb[5]=b1.y; xb[6]=b1.z; xb[7]=b1.w;
    } else {
        #pragma unroll
        for (int i = 0; i < EPT; i++) { xa[i] = 0.0f; xb[i] = 0.0f; }
    }
    if (t == 0) { x0A = xa[0]; x0B = xb[0]; }   // virtual state m[-1] = x[0]

    // ---- pass 1: local zero-init scans (two independent FMA chains) ----
    float FvA = 0.0f, FvB = 0.0f;
    #pragma unroll
    for (int i = 0; i < EPT; i++) {
        FvA = fmaf(aA, FvA, sA * xa[i]);
        FvB = fmaf(aB, FvB, sB * xb[i]);
    }

    float DA = aA; DA*=DA; DA*=DA; DA*=DA;     // aA^8
    float DB = aB; DB*=DB; DB*=DB; DB*=DB;     // aB^8

    // ---- level 2: fused warp scans ----
    float vA = FvA, vB = FvB;
    float pwA = DA, pwB = DB;
    float plA = 1.0f, plB = 1.0f;              // D^lane accumulators
    #pragma unroll
    for (int off = 1; off < 32; off <<= 1) {
        float uA = __shfl_up_sync(0xFFFFFFFFu, vA, off);
        float uB = __shfl_up_sync(0xFFFFFFFFu, vB, off);
        if (lane & off) { plA *= pwA; plB *= pwB; }
        if (lane >= off) { vA = fmaf(pwA, uA, vA); vB = fmaf(pwB, uB, vB); }
        pwA *= pwA; pwB *= pwB;
    }
    const float DwA = pwA, DwB = pwB;          // a^256 per row

    if (lane == 31) { totA[wid] = vA; totB[wid] = vB; }

    // exclusive-within-warp values
    float vexA = __shfl_up_sync(0xFFFFFFFFu, vA, 1);
    float vexB = __shfl_up_sync(0xFFFFFFFFu, vB, 1);
    if (lane == 0) { vexA = 0.0f; vexB = 0.0f; }

    __syncthreads();

    // ---- level 3: every warp redundantly scans the 32 warp totals (fused) ----
    float wA = totA[lane], wB = totB[lane];
    float qA = DwA, qB = DwB;
    float qlA = 1.0f, qlB = 1.0f;              // Dw^lane accumulators
    #pragma unroll
    for (int off = 1; off < 32; off <<= 1) {
        float uA = __shfl_up_sync(0xFFFFFFFFu, wA, off);
        float uB = __shfl_up_sync(0xFFFFFFFFu, wB, off);
        if (lane & off) { qlA *= qA; qlB *= qB; }
        if (lane >= off) { wA = fmaf(qA, uA, wA); wB = fmaf(qB, uB, wB); }
        qA *= qA; qB *= qB;
    }
    // pick exclusive prefix + Dw^wid at lane == wid via shuffle
    const int src = (wid == 0) ? 0 : (wid - 1);
    float exA = __shfl_sync(0xFFFFFFFFu, wA, src);
    float exB = __shfl_sync(0xFFFFFFFFu, wB, src);
    float plwA = __shfl_sync(0xFFFFFFFFu, qlA * DwA, src);  // Dw^(src+1) = Dw^wid
    float plwB = __shfl_sync(0xFFFFFFFFu, qlB * DwB, src);
    if (wid == 0) { exA = 0.0f; exB = 0.0f; plwA = 1.0f; plwB = 1.0f; }

    const float carryA = fmaf(plA, fmaf(plwA, x0A, exA), vexA);
    const float carryB = fmaf(plB, fmaf(plwB, x0B, exB), vexB);

    // ---- pass 2: fused replay + epilogue (two MUFU chains interleaved) ----
    if (active) {
        float mA = carryA, mB = carryB;
        #pragma unroll
        for (int i = 0; i < EPT; i++) {
            mA = fmaf(aA, mA, sA * xa[i]);
            mB = fmaf(aB, mB, sB * xb[i]);
            float lA = f_lg2(EPS_C + mA);
            float lB = f_lg2(EPS_C + mB);
            float iA = f_ex2(-ALPHA_C * lA);
            float iB = f_ex2(-ALPHA_C * lB);
            float uA2 = fmaf(xa[i], iA, DELTA_C);
            float uB2 = fmaf(xb[i], iB, DELTA_C);
            xa[i] = f_sqrt(uA2) - SQRT_DELTA;
            xb[i] = f_sqrt(uB2) - SQRT_DELTA;
        }
        float4* poA = (float4*)(out + (long long)rowA * TT + base);
        float4* poB = (float4*)(out + (long long)rowB * TT + base);
        poA[0] = make_float4(xa[0], xa[1], xa[2], xa[3]);
        poA[1] = make_float4(xa[4], xa[5], xa[6], xa[7]);
        poB[0] = make_float4(xb[0], xb[1], xb[2], xb[3]);
        poB[1] = make_float4(xb[4], xb[5], xb[6], xb[7]);
    }
}

extern "C" void kernel_launch(void* const* d_in, const int* in_sizes, int n_in,
                              void* d_out, int out_size)
{
    int xi = 0, si = 1;
    if (n_in >= 2 && in_sizes[0] < in_sizes[1]) { xi = 1; si = 0; }

    const float* x     = (const float*)d_in[xi];
    const float* log_s = (const float*)d_in[si];
    float*       out   = (float*)d_out;

    const int F    = in_sizes[si];           // 128
    const int rows = in_sizes[xi] / TT;      // B*F = 4096

    pcen_kernel<<<(rows + 1) / 2, NTH>>>(x, log_s, out, F, rows);
}

// round 7
// speedup vs baseline: 1.1304x; 1.1304x over previous
#include <cuda_runtime.h>
#include <cuda_bf16.h>

// PCEN via exact parallel linear-recurrence scan (constant per-row decay a=1-s).
// R7: one row per CTA, row split into two half-rows of 4000. Thread t owns
// 4-element segments [4t,4t+4) and [4000+4t, 4000+4t+4), so every LDG.128 /
// STG.128 is perfectly coalesced (lanes at consecutive 16B -> 4 full lines per
// warp instr, full-sector stores). Two fused scan chains share all decay
// constants; chunk1 is seeded with S0 = m[3999], reconstructed exactly from
// the redundant level-3 scan + thread 999's published within-warp partial.

#define TT    8000
#define HALF  4000
#define EPT   4
#define NTH   1024
#define NWARP (NTH/32)
#define ALPHA_C 0.98f
#define DELTA_C 2.0f
#define EPS_C   1e-6f
#define SQRT_DELTA 1.41421356237f
#define LOG2E 1.44269504089f

__device__ __forceinline__ float f_lg2(float x) {
    float r; asm("lg2.approx.f32 %0, %1;" : "=f"(r) : "f"(x)); return r;
}
__device__ __forceinline__ float f_ex2(float x) {
    float r; asm("ex2.approx.f32 %0, %1;" : "=f"(r) : "f"(x)); return r;
}
__device__ __forceinline__ float f_sqrt(float x) {
    float r; asm("sqrt.approx.f32 %0, %1;" : "=f"(r) : "f"(x)); return r;
}

__global__ __launch_bounds__(NTH, 2)
void pcen_kernel(const float* __restrict__ x,
                 const float* __restrict__ log_s,
                 float* __restrict__ out,
                 int F)
{
    const int row = blockIdx.x;
    const float s = f_ex2(LOG2E * __ldg(log_s + (row % F)));
    const float a = 1.0f - s;

    const float* xr   = x   + (long long)row * TT;
    float*       orow = out + (long long)row * TT;

    const int t    = threadIdx.x;
    const bool active = (t < HALF / EPT);       // threads 0..999
    const int lane = t & 31;
    const int wid  = t >> 5;

    __shared__ float tot0[NWARP], tot1[NWARP];
    __shared__ float x0sh, val7sh;

    // ---- perfectly coalesced loads: 2x LDG.128, lanes at consecutive 16B ----
    float c0[EPT], c1[EPT];
    if (active) {
        float4 v0 = *(const float4*)(xr + 4 * t);
        float4 v1 = *(const float4*)(xr + HALF + 4 * t);
        c0[0]=v0.x; c0[1]=v0.y; c0[2]=v0.z; c0[3]=v0.w;
        c1[0]=v1.x; c1[1]=v1.y; c1[2]=v1.z; c1[3]=v1.w;
    } else {
        #pragma unroll
        for (int i = 0; i < EPT; i++) { c0[i] = 0.0f; c1[i] = 0.0f; }
    }
    if (t == 0) x0sh = c0[0];                   // virtual state m[-1] = x[0]

    // ---- pass 1: local zero-init scans (two chains, shared constants) ----
    float Fv0 = 0.0f, Fv1 = 0.0f;
    #pragma unroll
    for (int i = 0; i < EPT; i++) {
        Fv0 = fmaf(a, Fv0, s * c0[i]);
        Fv1 = fmaf(a, Fv1, s * c1[i]);
    }

    float a2 = a * a;
    const float D  = a2 * a2;                   // a^4 (per-segment decay)

    // ---- level 2: fused warp scan ----
    float v0 = Fv0, v1 = Fv1;
    float pw = D;                               // D^(2^k)
    float pl = 1.0f;                            // D^lane
    #pragma unroll
    for (int off = 1; off < 32; off <<= 1) {
        float u0 = __shfl_up_sync(0xFFFFFFFFu, v0, off);
        float u1 = __shfl_up_sync(0xFFFFFFFFu, v1, off);
        if (lane & off) pl *= pw;
        if (lane >= off) { v0 = fmaf(pw, u0, v0); v1 = fmaf(pw, u1, v1); }
        pw *= pw;
    }
    const float Dw = pw;                        // D^32 = a^128

    if (lane == 31) { tot0[wid] = v0; tot1[wid] = v1; }
    if (t == 999)   val7sh = v0;                // inclusive partial at seg 999

    float vex0 = __shfl_up_sync(0xFFFFFFFFu, v0, 1);
    float vex1 = __shfl_up_sync(0xFFFFFFFFu, v1, 1);
    if (lane == 0) { vex0 = 0.0f; vex1 = 0.0f; }

    __syncthreads();

    // ---- level 3: every warp redundantly scans the 32 warp totals (fused) ----
    float w0 = tot0[lane], w1 = tot1[lane];
    float q  = Dw;
    float ql = 1.0f;                            // Dw^lane
    #pragma unroll
    for (int off = 1; off < 32; off <<= 1) {
        float u0 = __shfl_up_sync(0xFFFFFFFFu, w0, off);
        float u1 = __shfl_up_sync(0xFFFFFFFFu, w1, off);
        if (lane & off) ql *= q;
        if (lane >= off) { w0 = fmaf(q, u0, w0); w1 = fmaf(q, u1, w1); }
        q *= q;
    }

    // exclusive level-3 prefix + Dw^wid for this thread's warp
    const int src = (wid == 0) ? 0 : (wid - 1);
    float ex0 = __shfl_sync(0xFFFFFFFFu, w0, src);
    float ex1 = __shfl_sync(0xFFFFFFFFu, w1, src);
    float plw = __shfl_sync(0xFFFFFFFFu, ql * Dw, src);   // Dw^wid
    if (wid == 0) { ex0 = 0.0f; ex1 = 0.0f; plw = 1.0f; }

    // reconstruct S0 = m[3999]: state entering warp 31 of chunk0, advanced
    // through lanes 0..7 (8 segments: D^8 = a^32) plus val7.
    const float x0    = x0sh;
    float e31   = __shfl_sync(0xFFFFFFFFu, w0, 30);       // incl. scan @ lane 30
    float plw31 = __shfl_sync(0xFFFFFFFFu, ql * Dw, 30);  // Dw^31
    float D2 = D * D, D4 = D2 * D2, D8 = D4 * D4;         // a^32
    const float S0 = fmaf(D8, fmaf(plw31, x0, e31), val7sh);

    const float carry0 = fmaf(pl, fmaf(plw, x0, ex0), vex0);
    const float carry1 = fmaf(pl, fmaf(plw, S0, ex1), vex1);

    // ---- pass 2: fused replay + epilogue, coalesced full-line stores ----
    if (active) {
        float m0 = carry0, m1 = carry1;
        #pragma unroll
        for (int i = 0; i < EPT; i++) {
            m0 = fmaf(a, m0, s * c0[i]);
            m1 = fmaf(a, m1, s * c1[i]);
            float l0 = f_lg2(EPS_C + m0);
            float l1 = f_lg2(EPS_C + m1);
            float i0 = f_ex2(-ALPHA_C * l0);
            float i1 = f_ex2(-ALPHA_C * l1);
            float u0 = fmaf(c0[i], i0, DELTA_C);
            float u1 = fmaf(c1[i], i1, DELTA_C);
            c0[i] = f_sqrt(u0) - SQRT_DELTA;
            c1[i] = f_sqrt(u1) - SQRT_DELTA;
        }
        *(float4*)(orow + 4 * t)        = make_float4(c0[0], c0[1], c0[2], c0[3]);
        *(float4*)(orow + HALF + 4 * t) = make_float4(c1[0], c1[1], c1[2], c1[3]);
    }
}

extern "C" void kernel_launch(void* const* d_in, const int* in_sizes, int n_in,
                              void* d_out, int out_size)
{
    int xi = 0, si = 1;
    if (n_in >= 2 && in_sizes[0] < in_sizes[1]) { xi = 1; si = 0; }

    const float* x     = (const float*)d_in[xi];
    const float* log_s = (const float*)d_in[si];
    float*       out   = (float*)d_out;

    const int F    = in_sizes[si];           // 128
    const int rows = in_sizes[xi] / TT;      // B*F = 4096

    pcen_kernel<<<rows, NTH>>>(x, log_s, out, F);
}